// round 14
// baseline (speedup 1.0000x reference)
#include <cuda_runtime.h>
#include <mma.h>
#include <cstdint>

using namespace nvcuda;

// ---------------- problem constants ----------------
#define DM      512                 // d_model
#define SEQ     96
#define BATCH   512
#define NROWS   (BATCH * SEQ)       // 49152
#define CUTOFF  16                  // FREQ(49) // 3

// ---------------- device scratch (allowed: __device__ globals) ----------------
__device__ float  g_xl[NROWS * DM];      // L * x
__device__ float  g_xh[NROWS * DM];      // H * x
__device__ float  g_xlow2[NROWS * DM];   // xl @ Wl + bl
__device__ float  g_xhigh2[NROWS * DM];  // xh @ Wh + bh
__device__ float  g_gpre[NROWS * DM];    // xl@Wlg + xh@Whg + biasg
__device__ float  g_Wlg[DM * DM];        // Wl @ Wg[0:512,:]
__device__ float  g_Whg[DM * DM];        // Wh @ Wg[512:1024,:]
__device__ float  g_biasg[DM];           // bl@Wg_top + bh@Wg_bot + bg
__device__ float2 g_hpair[SEQ];          // (h_low[u], h_high[u])

// ---------------- small kernel: circular conv taps from freq_weights ----------------
__global__ void h_kernel(const float* __restrict__ fw)
{
    int n = threadIdx.x;
    if (n >= SEQ) return;
    const float c0 = 6.2831853071795864769f / (float)SEQ;
    float hl = fw[0];
    for (int k = 1; k < CUTOFF; k++)
        hl += 2.0f * fw[k] * cosf((float)((k * n) % SEQ) * c0);
    float hh = 0.0f;
    for (int k = CUTOFF; k < 48; k++)
        hh += 2.0f * fw[k] * cosf((float)((k * n) % SEQ) * c0);
    hh += fw[48] * cosf((float)((48 * n) % SEQ) * c0);   // Nyquist, counted once
    g_hpair[n] = make_float2(hl * (1.0f / SEQ), hh * (1.0f / SEQ));
}

// ---------------- small kernel: folded gate bias ----------------
// biasg[e] = bg[e] + sum_d bl[d]*Wg[d,e] + sum_d bh[d]*Wg[512+d,e]
__global__ void biasg_kernel(const float* __restrict__ bl,
                             const float* __restrict__ bh,
                             const float* __restrict__ Wg,
                             const float* __restrict__ bg)
{
    int e = blockIdx.x * 128 + threadIdx.x;
    if (e >= DM) return;
    float acc = bg[e];
    for (int d = 0; d < DM; d++)       acc += bl[d] * Wg[d * DM + e];
    for (int d = 0; d < DM; d++)       acc += bh[d] * Wg[(DM + d) * DM + e];
    g_biasg[e] = acc;
}

// ---------------- filter kernel: circular conv along seq (fp32) ----------------
// xl[b,s,d] = sum_u h_low[u]  * x[b,(s-u)%96,d]
// xh[b,s,d] = sum_u h_high[u] * x[b,(s-u)%96,d]
#define FCHUNK 64
__global__ __launch_bounds__(256)
void filter_kernel(const float* __restrict__ x)
{
    __shared__ float  xs[SEQ * FCHUNK];
    __shared__ float2 hs[SEQ];
    const int b     = blockIdx.y;
    const int dbase = blockIdx.x * FCHUNK;
    const int tid   = threadIdx.x;
    if (tid < SEQ) hs[tid] = g_hpair[tid];

    const float* xb = x + (size_t)b * SEQ * DM + dbase;
#pragma unroll
    for (int it = 0; it < 6; it++) {               // 96*16 float4 / 256 threads
        int i = tid + it * 256;
        int s = i >> 4;
        int c = (i & 15) * 4;
        *(float4*)&xs[s * FCHUNK + c] = *(const float4*)(xb + (size_t)s * DM + c);
    }
    __syncthreads();

    float* xlb = g_xl + (size_t)b * SEQ * DM + dbase;
    float* xhb = g_xh + (size_t)b * SEQ * DM + dbase;
#pragma unroll
    for (int it = 0; it < 6; it++) {
        int i = tid + it * 256;
        int s = i >> 4;
        int c = (i & 15) * 4;
        float4 al = make_float4(0.f, 0.f, 0.f, 0.f);
        float4 ah = make_float4(0.f, 0.f, 0.f, 0.f);
        int t = s;                                  // t = (s - u) mod 96
#pragma unroll 4
        for (int u = 0; u < SEQ; u++) {
            float2 h  = hs[u];
            float4 xv = *(const float4*)&xs[t * FCHUNK + c];
            al.x += h.x * xv.x; al.y += h.x * xv.y; al.z += h.x * xv.z; al.w += h.x * xv.w;
            ah.x += h.y * xv.x; ah.y += h.y * xv.y; ah.z += h.y * xv.z; ah.w += h.y * xv.w;
            t--; if (t < 0) t = SEQ - 1;
        }
        *(float4*)(xlb + (size_t)s * DM + c) = al;
        *(float4*)(xhb + (size_t)s * DM + c) = ah;
    }
}

// ---------------- tf32 wmma GEMM body ----------------
// C[M,512] = A[M,512] @ B[512,512]  (+bias[col]) (+= when ACC)
// All leading dims are 512. Grid: (512/64, M/128), block 256 (8 warps, 4x2).
#define GBM 128
#define GBN 64
#define GBK 32
#define LDAS 40
#define LDBS 72

template<bool ACC, bool BIAS>
__device__ __forceinline__
void gemm_body(const float* __restrict__ A, const float* __restrict__ B,
               float* __restrict__ C, const float* __restrict__ bias)
{
    __shared__ float sm[10240];                    // max(As+Bs, staging)
    float* As = sm;                                // [128][40]
    float* Bs = sm + GBM * LDAS;                   // [32][72]

    const int bm   = blockIdx.y * GBM;
    const int bn   = blockIdx.x * GBN;
    const int tid  = threadIdx.x;
    const int warp = tid >> 5;
    const int lane = tid & 31;
    const int wm   = (warp >> 1) * 32;             // 0,32,64,96
    const int wn   = (warp & 1) * 32;              // 0,32

    wmma::fragment<wmma::accumulator, 16, 16, 8, float> acc[2][2];
#pragma unroll
    for (int i = 0; i < 2; i++)
#pragma unroll
        for (int j = 0; j < 2; j++) {
            if (ACC)
                wmma::load_matrix_sync(acc[i][j],
                    C + (size_t)(bm + wm + i * 16) * DM + bn + wn + j * 16,
                    DM, wmma::mem_row_major);
            else
                wmma::fill_fragment(acc[i][j], 0.0f);
        }

    for (int k0 = 0; k0 < DM; k0 += GBK) {
        // A tile: 128x32 = 1024 float4
#pragma unroll
        for (int it = 0; it < 4; it++) {
            int i = tid + it * 256;
            int r = i >> 3;
            int c = (i & 7) * 4;
            float4 v = *(const float4*)(A + (size_t)(bm + r) * DM + k0 + c);
            *(float4*)&As[r * LDAS + c] = v;
        }
        // B tile: 32x64 = 512 float4
#pragma unroll
        for (int it = 0; it < 2; it++) {
            int i = tid + it * 256;
            int r = i >> 4;
            int c = (i & 15) * 4;
            float4 v = *(const float4*)(B + (size_t)(k0 + r) * DM + bn + c);
            *(float4*)&Bs[r * LDBS + c] = v;
        }
        __syncthreads();
#pragma unroll
        for (int kk = 0; kk < GBK; kk += 8) {
            wmma::fragment<wmma::matrix_a, 16, 16, 8, wmma::precision::tf32, wmma::row_major> af[2];
            wmma::fragment<wmma::matrix_b, 16, 16, 8, wmma::precision::tf32, wmma::row_major> bf[2];
#pragma unroll
            for (int i = 0; i < 2; i++) {
                wmma::load_matrix_sync(af[i], &As[(wm + i * 16) * LDAS + kk], LDAS);
#pragma unroll
                for (int t = 0; t < af[i].num_elements; t++)
                    af[i].x[t] = wmma::__float_to_tf32(af[i].x[t]);
            }
#pragma unroll
            for (int j = 0; j < 2; j++) {
                wmma::load_matrix_sync(bf[j], &Bs[kk * LDBS + wn + j * 16], LDBS);
#pragma unroll
                for (int t = 0; t < bf[j].num_elements; t++)
                    bf[j].x[t] = wmma::__float_to_tf32(bf[j].x[t]);
            }
#pragma unroll
            for (int i = 0; i < 2; i++)
#pragma unroll
                for (int j = 0; j < 2; j++)
                    wmma::mma_sync(acc[i][j], af[i], bf[j], acc[i][j]);
        }
        __syncthreads();
    }

    if (!BIAS) {
#pragma unroll
        for (int i = 0; i < 2; i++)
#pragma unroll
            for (int j = 0; j < 2; j++)
                wmma::store_matrix_sync(
                    C + (size_t)(bm + wm + i * 16) * DM + bn + wn + j * 16,
                    acc[i][j], DM, wmma::mem_row_major);
    } else {
        // stage through smem to add per-column bias with coalesced stores
        float* stg = sm + warp * 32 * 40;          // per-warp 32x32, ld=40
#pragma unroll
        for (int i = 0; i < 2; i++)
#pragma unroll
            for (int j = 0; j < 2; j++)
                wmma::store_matrix_sync(&stg[(i * 16) * 40 + j * 16],
                                        acc[i][j], 40, wmma::mem_row_major);
        __syncwarp();
        int gc = bn + wn + lane;
        float bv = bias[gc];
#pragma unroll
        for (int r = 0; r < 32; r++)
            C[(size_t)(bm + wm + r) * DM + gc] = stg[r * 40 + lane] + bv;
    }
}

// Wrapper kernels bind the __device__ global scratch directly (no host symbol lookups).
__global__ __launch_bounds__(256) void gemm_wlg(const float* Wl, const float* Wg)
{ gemm_body<false, false>(Wl, Wg, g_Wlg, nullptr); }

__global__ __launch_bounds__(256) void gemm_whg(const float* Wh, const float* Wg)
{ gemm_body<false, false>(Wh, Wg + DM * DM, g_Whg, nullptr); }

__global__ __launch_bounds__(256) void gemm_xlow(const float* Wl, const float* bl)
{ gemm_body<false, true>(g_xl, Wl, g_xlow2, bl); }

__global__ __launch_bounds__(256) void gemm_xhigh(const float* Wh, const float* bh)
{ gemm_body<false, true>(g_xh, Wh, g_xhigh2, bh); }

__global__ __launch_bounds__(256) void gemm_gpre_a()
{ gemm_body<false, true>(g_xl, g_Wlg, g_gpre, g_biasg); }

__global__ __launch_bounds__(256) void gemm_gpre_b()
{ gemm_body<true, false>(g_xh, g_Whg, g_gpre, nullptr); }

// ---------------- fused gate + residual + LayerNorm ----------------
__global__ __launch_bounds__(256)
void final_kernel(const float* __restrict__ x,
                  const float* __restrict__ gamma,
                  const float* __restrict__ beta,
                  float* __restrict__ out)
{
    const int r   = blockIdx.x;
    const size_t base = (size_t)r * DM;
    const int tid = threadIdx.x;
    const int c   = tid * 2;

    float2 xv = *(const float2*)(x        + base + c);
    float2 lv = *(const float2*)(g_xlow2  + base + c);
    float2 hv = *(const float2*)(g_xhigh2 + base + c);
    float2 gv = *(const float2*)(g_gpre   + base + c);

    float g0 = 1.0f / (1.0f + __expf(-gv.x));
    float g1 = 1.0f / (1.0f + __expf(-gv.y));
    float y0 = xv.x + g0 * lv.x + (1.0f - g0) * hv.x;
    float y1 = xv.y + g1 * lv.y + (1.0f - g1) * hv.y;

    float s1 = y0 + y1;
    float s2 = y0 * y0 + y1 * y1;
#pragma unroll
    for (int o = 16; o > 0; o >>= 1) {
        s1 += __shfl_xor_sync(0xffffffffu, s1, o);
        s2 += __shfl_xor_sync(0xffffffffu, s2, o);
    }
    __shared__ float rs1[8], rs2[8];
    int warp = tid >> 5, lane = tid & 31;
    if (lane == 0) { rs1[warp] = s1; rs2[warp] = s2; }
    __syncthreads();
    float t1 = 0.f, t2 = 0.f;
#pragma unroll
    for (int w = 0; w < 8; w++) { t1 += rs1[w]; t2 += rs2[w]; }

    float mu   = t1 * (1.0f / DM);
    float var  = t2 * (1.0f / DM) - mu * mu;
    float rstd = rsqrtf(var + 1e-5f);

    float2 gm = *(const float2*)(gamma + c);
    float2 bt = *(const float2*)(beta  + c);
    float2 o2;
    o2.x = (y0 - mu) * rstd * gm.x + bt.x;
    o2.y = (y1 - mu) * rstd * gm.y + bt.y;
    *(float2*)(out + base + c) = o2;
}

// ---------------- launch ----------------
extern "C" void kernel_launch(void* const* d_in, const int* in_sizes, int n_in,
                              void* d_out, int out_size)
{
    const float* x     = (const float*)d_in[0];
    const float* fw    = (const float*)d_in[1];
    const float* Wl    = (const float*)d_in[2];
    const float* bl    = (const float*)d_in[3];
    const float* Wh    = (const float*)d_in[4];
    const float* bh    = (const float*)d_in[5];
    const float* Wg    = (const float*)d_in[6];
    const float* bg    = (const float*)d_in[7];
    const float* gamma = (const float*)d_in[8];
    const float* beta  = (const float*)d_in[9];
    float* out = (float*)d_out;

    // 1. conv taps + folded gate bias + folded weight products
    h_kernel<<<1, 128>>>(fw);
    biasg_kernel<<<4, 128>>>(bl, bh, Wg, bg);
    dim3 gsmall(DM / GBN, DM / GBM);               // (8,4)
    gemm_wlg<<<gsmall, 256>>>(Wl, Wg);
    gemm_whg<<<gsmall, 256>>>(Wh, Wg);

    // 2. spectral split as circular conv along seq
    filter_kernel<<<dim3(DM / FCHUNK, BATCH), 256>>>(x);

    // 3. big GEMMs (tf32 tensor cores)
    dim3 gbig(DM / GBN, NROWS / GBM);              // (8,384)
    gemm_xlow <<<gbig, 256>>>(Wl, bl);
    gemm_xhigh<<<gbig, 256>>>(Wh, bh);
    gemm_gpre_a<<<gbig, 256>>>();
    gemm_gpre_b<<<gbig, 256>>>();

    // 4. gate + residual + LayerNorm
    final_kernel<<<NROWS, 256>>>(x, gamma, beta, out);
}

// round 15
// speedup vs baseline: 1.0007x; 1.0007x over previous
#include <cuda_runtime.h>
#include <mma.h>
#include <cstdint>

using namespace nvcuda;

// ---------------- problem constants ----------------
#define DM      512                 // d_model
#define SEQ     96
#define BATCH   512
#define NROWS   (BATCH * SEQ)       // 49152
#define CUTOFF  16                  // FREQ(49) // 3

// ---------------- device scratch (allowed: __device__ globals) ----------------
__device__ float  g_xl[NROWS * DM];      // L * x
__device__ float  g_xh[NROWS * DM];      // H * x
__device__ float  g_xlow2[NROWS * DM];   // xl @ Wl + bl
__device__ float  g_xhigh2[NROWS * DM];  // xh @ Wh + bh
__device__ float  g_gpre[NROWS * DM];    // xl@Wlg + xh@Whg + biasg
__device__ float  g_Wlg[DM * DM];        // Wl @ Wg[0:512,:]
__device__ float  g_Whg[DM * DM];        // Wh @ Wg[512:1024,:]
__device__ float  g_biasg[DM];           // bl@Wg_top + bh@Wg_bot + bg
__device__ float2 g_hpair[SEQ];          // (h_low[u], h_high[u])

// ---------------- small kernel: circular conv taps from freq_weights ----------------
__global__ void h_kernel(const float* __restrict__ fw)
{
    int n = threadIdx.x;
    if (n >= SEQ) return;
    const float c0 = 6.2831853071795864769f / (float)SEQ;
    float hl = fw[0];
    for (int k = 1; k < CUTOFF; k++)
        hl += 2.0f * fw[k] * cosf((float)((k * n) % SEQ) * c0);
    float hh = 0.0f;
    for (int k = CUTOFF; k < 48; k++)
        hh += 2.0f * fw[k] * cosf((float)((k * n) % SEQ) * c0);
    hh += fw[48] * cosf((float)((48 * n) % SEQ) * c0);   // Nyquist, counted once
    g_hpair[n] = make_float2(hl * (1.0f / SEQ), hh * (1.0f / SEQ));
}

// ---------------- small kernel: folded gate bias ----------------
// biasg[e] = bg[e] + sum_d bl[d]*Wg[d,e] + sum_d bh[d]*Wg[512+d,e]
__global__ void biasg_kernel(const float* __restrict__ bl,
                             const float* __restrict__ bh,
                             const float* __restrict__ Wg,
                             const float* __restrict__ bg)
{
    int e = blockIdx.x * 128 + threadIdx.x;
    if (e >= DM) return;
    float acc = bg[e];
    for (int d = 0; d < DM; d++)       acc += bl[d] * Wg[d * DM + e];
    for (int d = 0; d < DM; d++)       acc += bh[d] * Wg[(DM + d) * DM + e];
    g_biasg[e] = acc;
}

// ---------------- filter kernel: circular conv along seq (fp32) ----------------
// xl[b,s,d] = sum_u h_low[u]  * x[b,(s-u)%96,d]
// xh[b,s,d] = sum_u h_high[u] * x[b,(s-u)%96,d]
#define FCHUNK 64
__global__ __launch_bounds__(256)
void filter_kernel(const float* __restrict__ x)
{
    __shared__ float  xs[SEQ * FCHUNK];
    __shared__ float2 hs[SEQ];
    const int b     = blockIdx.y;
    const int dbase = blockIdx.x * FCHUNK;
    const int tid   = threadIdx.x;
    if (tid < SEQ) hs[tid] = g_hpair[tid];

    const float* xb = x + (size_t)b * SEQ * DM + dbase;
#pragma unroll
    for (int it = 0; it < 6; it++) {               // 96*16 float4 / 256 threads
        int i = tid + it * 256;
        int s = i >> 4;
        int c = (i & 15) * 4;
        *(float4*)&xs[s * FCHUNK + c] = *(const float4*)(xb + (size_t)s * DM + c);
    }
    __syncthreads();

    float* xlb = g_xl + (size_t)b * SEQ * DM + dbase;
    float* xhb = g_xh + (size_t)b * SEQ * DM + dbase;
#pragma unroll
    for (int it = 0; it < 6; it++) {
        int i = tid + it * 256;
        int s = i >> 4;
        int c = (i & 15) * 4;
        float4 al = make_float4(0.f, 0.f, 0.f, 0.f);
        float4 ah = make_float4(0.f, 0.f, 0.f, 0.f);
        int t = s;                                  // t = (s - u) mod 96
#pragma unroll 4
        for (int u = 0; u < SEQ; u++) {
            float2 h  = hs[u];
            float4 xv = *(const float4*)&xs[t * FCHUNK + c];
            al.x += h.x * xv.x; al.y += h.x * xv.y; al.z += h.x * xv.z; al.w += h.x * xv.w;
            ah.x += h.y * xv.x; ah.y += h.y * xv.y; ah.z += h.y * xv.z; ah.w += h.y * xv.w;
            t--; if (t < 0) t = SEQ - 1;
        }
        *(float4*)(xlb + (size_t)s * DM + c) = al;
        *(float4*)(xhb + (size_t)s * DM + c) = ah;
    }
}

// ---------------- tf32 wmma GEMM body ----------------
// C[M,512] = A[M,512] @ B[512,512]  (+bias[col]) (+= when ACC)
// All leading dims are 512. Grid: (512/64, M/128), block 256 (8 warps, 4x2).
#define GBM 128
#define GBN 64
#define GBK 32
#define LDAS 40
#define LDBS 72

template<bool ACC, bool BIAS>
__device__ __forceinline__
void gemm_body(const float* __restrict__ A, const float* __restrict__ B,
               float* __restrict__ C, const float* __restrict__ bias)
{
    __shared__ float sm[10240];                    // max(As+Bs, staging)
    float* As = sm;                                // [128][40]
    float* Bs = sm + GBM * LDAS;                   // [32][72]

    const int bm   = blockIdx.y * GBM;
    const int bn   = blockIdx.x * GBN;
    const int tid  = threadIdx.x;
    const int warp = tid >> 5;
    const int lane = tid & 31;
    const int wm   = (warp >> 1) * 32;             // 0,32,64,96
    const int wn   = (warp & 1) * 32;              // 0,32

    wmma::fragment<wmma::accumulator, 16, 16, 8, float> acc[2][2];
#pragma unroll
    for (int i = 0; i < 2; i++)
#pragma unroll
        for (int j = 0; j < 2; j++) {
            if (ACC)
                wmma::load_matrix_sync(acc[i][j],
                    C + (size_t)(bm + wm + i * 16) * DM + bn + wn + j * 16,
                    DM, wmma::mem_row_major);
            else
                wmma::fill_fragment(acc[i][j], 0.0f);
        }

    for (int k0 = 0; k0 < DM; k0 += GBK) {
        // A tile: 128x32 = 1024 float4
#pragma unroll
        for (int it = 0; it < 4; it++) {
            int i = tid + it * 256;
            int r = i >> 3;
            int c = (i & 7) * 4;
            float4 v = *(const float4*)(A + (size_t)(bm + r) * DM + k0 + c);
            *(float4*)&As[r * LDAS + c] = v;
        }
        // B tile: 32x64 = 512 float4
#pragma unroll
        for (int it = 0; it < 2; it++) {
            int i = tid + it * 256;
            int r = i >> 4;
            int c = (i & 15) * 4;
            float4 v = *(const float4*)(B + (size_t)(k0 + r) * DM + bn + c);
            *(float4*)&Bs[r * LDBS + c] = v;
        }
        __syncthreads();
#pragma unroll
        for (int kk = 0; kk < GBK; kk += 8) {
            wmma::fragment<wmma::matrix_a, 16, 16, 8, wmma::precision::tf32, wmma::row_major> af[2];
            wmma::fragment<wmma::matrix_b, 16, 16, 8, wmma::precision::tf32, wmma::row_major> bf[2];
#pragma unroll
            for (int i = 0; i < 2; i++) {
                wmma::load_matrix_sync(af[i], &As[(wm + i * 16) * LDAS + kk], LDAS);
#pragma unroll
                for (int t = 0; t < af[i].num_elements; t++)
                    af[i].x[t] = wmma::__float_to_tf32(af[i].x[t]);
            }
#pragma unroll
            for (int j = 0; j < 2; j++) {
                wmma::load_matrix_sync(bf[j], &Bs[kk * LDBS + wn + j * 16], LDBS);
#pragma unroll
                for (int t = 0; t < bf[j].num_elements; t++)
                    bf[j].x[t] = wmma::__float_to_tf32(bf[j].x[t]);
            }
#pragma unroll
            for (int i = 0; i < 2; i++)
#pragma unroll
                for (int j = 0; j < 2; j++)
                    wmma::mma_sync(acc[i][j], af[i], bf[j], acc[i][j]);
        }
        __syncthreads();
    }

    if (!BIAS) {
#pragma unroll
        for (int i = 0; i < 2; i++)
#pragma unroll
            for (int j = 0; j < 2; j++)
                wmma::store_matrix_sync(
                    C + (size_t)(bm + wm + i * 16) * DM + bn + wn + j * 16,
                    acc[i][j], DM, wmma::mem_row_major);
    } else {
        // stage through smem to add per-column bias with coalesced stores
        float* stg = sm + warp * 32 * 40;          // per-warp 32x32, ld=40
#pragma unroll
        for (int i = 0; i < 2; i++)
#pragma unroll
            for (int j = 0; j < 2; j++)
                wmma::store_matrix_sync(&stg[(i * 16) * 40 + j * 16],
                                        acc[i][j], 40, wmma::mem_row_major);
        __syncwarp();
        int gc = bn + wn + lane;
        float bv = bias[gc];
#pragma unroll
        for (int r = 0; r < 32; r++)
            C[(size_t)(bm + wm + r) * DM + gc] = stg[r * 40 + lane] + bv;
    }
}

// Wrapper kernels bind the __device__ global scratch directly (no host symbol lookups).
__global__ __launch_bounds__(256) void gemm_wlg(const float* Wl, const float* Wg)
{ gemm_body<false, false>(Wl, Wg, g_Wlg, nullptr); }

__global__ __launch_bounds__(256) void gemm_whg(const float* Wh, const float* Wg)
{ gemm_body<false, false>(Wh, Wg + DM * DM, g_Whg, nullptr); }

__global__ __launch_bounds__(256) void gemm_xlow(const float* Wl, const float* bl)
{ gemm_body<false, true>(g_xl, Wl, g_xlow2, bl); }

__global__ __launch_bounds__(256) void gemm_xhigh(const float* Wh, const float* bh)
{ gemm_body<false, true>(g_xh, Wh, g_xhigh2, bh); }

__global__ __launch_bounds__(256) void gemm_gpre_a()
{ gemm_body<false, true>(g_xl, g_Wlg, g_gpre, g_biasg); }

__global__ __launch_bounds__(256) void gemm_gpre_b()
{ gemm_body<true, false>(g_xh, g_Whg, g_gpre, nullptr); }

// ---------------- fused gate + residual + LayerNorm ----------------
__global__ __launch_bounds__(256)
void final_kernel(const float* __restrict__ x,
                  const float* __restrict__ gamma,
                  const float* __restrict__ beta,
                  float* __restrict__ out)
{
    const int r   = blockIdx.x;
    const size_t base = (size_t)r * DM;
    const int tid = threadIdx.x;
    const int c   = tid * 2;

    float2 xv = *(const float2*)(x        + base + c);
    float2 lv = *(const float2*)(g_xlow2  + base + c);
    float2 hv = *(const float2*)(g_xhigh2 + base + c);
    float2 gv = *(const float2*)(g_gpre   + base + c);

    float g0 = 1.0f / (1.0f + __expf(-gv.x));
    float g1 = 1.0f / (1.0f + __expf(-gv.y));
    float y0 = xv.x + g0 * lv.x + (1.0f - g0) * hv.x;
    float y1 = xv.y + g1 * lv.y + (1.0f - g1) * hv.y;

    float s1 = y0 + y1;
    float s2 = y0 * y0 + y1 * y1;
#pragma unroll
    for (int o = 16; o > 0; o >>= 1) {
        s1 += __shfl_xor_sync(0xffffffffu, s1, o);
        s2 += __shfl_xor_sync(0xffffffffu, s2, o);
    }
    __shared__ float rs1[8], rs2[8];
    int warp = tid >> 5, lane = tid & 31;
    if (lane == 0) { rs1[warp] = s1; rs2[warp] = s2; }
    __syncthreads();
    float t1 = 0.f, t2 = 0.f;
#pragma unroll
    for (int w = 0; w < 8; w++) { t1 += rs1[w]; t2 += rs2[w]; }

    float mu   = t1 * (1.0f / DM);
    float var  = t2 * (1.0f / DM) - mu * mu;
    float rstd = rsqrtf(var + 1e-5f);

    float2 gm = *(const float2*)(gamma + c);
    float2 bt = *(const float2*)(beta  + c);
    float2 o2;
    o2.x = (y0 - mu) * rstd * gm.x + bt.x;
    o2.y = (y1 - mu) * rstd * gm.y + bt.y;
    *(float2*)(out + base + c) = o2;
}

// ---------------- launch ----------------
extern "C" void kernel_launch(void* const* d_in, const int* in_sizes, int n_in,
                              void* d_out, int out_size)
{
    const float* x     = (const float*)d_in[0];
    const float* fw    = (const float*)d_in[1];
    const float* Wl    = (const float*)d_in[2];
    const float* bl    = (const float*)d_in[3];
    const float* Wh    = (const float*)d_in[4];
    const float* bh    = (const float*)d_in[5];
    const float* Wg    = (const float*)d_in[6];
    const float* bg    = (const float*)d_in[7];
    const float* gamma = (const float*)d_in[8];
    const float* beta  = (const float*)d_in[9];
    float* out = (float*)d_out;

    // 1. conv taps + folded gate bias + folded weight products
    h_kernel<<<1, 128>>>(fw);
    biasg_kernel<<<4, 128>>>(bl, bh, Wg, bg);
    dim3 gsmall(DM / GBN, DM / GBM);               // (8,4)
    gemm_wlg<<<gsmall, 256>>>(Wl, Wg);
    gemm_whg<<<gsmall, 256>>>(Wh, Wg);

    // 2. spectral split as circular conv along seq
    filter_kernel<<<dim3(DM / FCHUNK, BATCH), 256>>>(x);

    // 3. big GEMMs (tf32 tensor cores)
    dim3 gbig(DM / GBN, NROWS / GBM);              // (8,384)
    gemm_xlow <<<gbig, 256>>>(Wl, bl);
    gemm_xhigh<<<gbig, 256>>>(Wh, bh);
    gemm_gpre_a<<<gbig, 256>>>();
    gemm_gpre_b<<<gbig, 256>>>();

    // 4. gate + residual + LayerNorm
    final_kernel<<<NROWS, 256>>>(x, gamma, beta, out);
}

// round 16
// speedup vs baseline: 1.1090x; 1.1082x over previous
#include <cuda_runtime.h>
#include <mma.h>
#include <cstdint>

using namespace nvcuda;

// ---------------- problem constants ----------------
#define DM      512
#define SEQ     96
#define BATCH   512
#define NROWS   (BATCH * SEQ)       // 49152
#define CUTOFF  16                  // FREQ(49) // 3

// ---------------- device scratch ----------------
__device__ float  g_xl[NROWS * DM];      // L*x   (tf32-rounded)
__device__ float  g_xh[NROWS * DM];      // H*x   (tf32-rounded)
__device__ float  g_xlow2[NROWS * DM];   // xl @ Wl           (no bias)
__device__ float  g_xhigh2[NROWS * DM];  // xh @ Wh           (no bias)
__device__ float  g_gl[NROWS * DM];      // xl @ Wlg          (no bias)
__device__ float  g_gh[NROWS * DM];      // xh @ Whg          (no bias)
__device__ float  g_Wlg[DM * DM];        // Wl @ Wg_top
__device__ float  g_Whg[DM * DM];        // Wh @ Wg_bot
__device__ float  g_Wlr[DM * DM];        // tf32-rounded Wl
__device__ float  g_Whr[DM * DM];        // tf32-rounded Wh
__device__ float  g_Wgr[2 * DM * DM];    // tf32-rounded Wg
__device__ float  g_biasg[DM];           // bl@Wg_top + bh@Wg_bot + bg
__device__ float2 g_hpair[SEQ];          // (h_low[u], h_high[u])

// ---------------- circular-conv taps from freq_weights ----------------
__global__ void h_kernel(const float* __restrict__ fw)
{
    int n = threadIdx.x;
    if (n >= SEQ) return;
    const float c0 = 6.2831853071795864769f / (float)SEQ;
    float hl = fw[0];
    for (int k = 1; k < CUTOFF; k++)
        hl += 2.0f * fw[k] * cosf((float)((k * n) % SEQ) * c0);
    float hh = 0.0f;
    for (int k = CUTOFF; k < 48; k++)
        hh += 2.0f * fw[k] * cosf((float)((k * n) % SEQ) * c0);
    hh += fw[48] * cosf((float)((48 * n) % SEQ) * c0);   // Nyquist once
    g_hpair[n] = make_float2(hl * (1.0f / SEQ), hh * (1.0f / SEQ));
}

// ---------------- folded gate bias ----------------
__global__ void biasg_kernel(const float* __restrict__ bl,
                             const float* __restrict__ bh,
                             const float* __restrict__ Wg,
                             const float* __restrict__ bg)
{
    int e = blockIdx.x * 128 + threadIdx.x;
    if (e >= DM) return;
    float acc = bg[e];
    for (int d = 0; d < DM; d++) acc += bl[d] * Wg[d * DM + e];
    for (int d = 0; d < DM; d++) acc += bh[d] * Wg[(DM + d) * DM + e];
    g_biasg[e] = acc;
}

// ---------------- tf32 rounding of weight operands ----------------
__global__ void round_w(const float* __restrict__ Wl,
                        const float* __restrict__ Wh,
                        const float* __restrict__ Wg)
{
    int i = blockIdx.x * 256 + threadIdx.x;          // 262144 threads exactly
    g_Wlr[i]           = wmma::__float_to_tf32(Wl[i]);
    g_Whr[i]           = wmma::__float_to_tf32(Wh[i]);
    g_Wgr[i]           = wmma::__float_to_tf32(Wg[i]);
    g_Wgr[i + DM * DM] = wmma::__float_to_tf32(Wg[i + DM * DM]);
}

// ---------------- filter: circular conv along seq, symmetric taps ----------------
// h[u] == h[96-u]  =>  al = h0*x[s] + h48*x[s-48] + sum_{u=1..47} h[u]*(x[s-u]+x[s+u])
#define FCHUNK 64
__global__ __launch_bounds__(256)
void filter_kernel(const float* __restrict__ x)
{
    __shared__ float  xs[SEQ * FCHUNK];
    __shared__ float2 hs[SEQ];
    const int b     = blockIdx.y;
    const int dbase = blockIdx.x * FCHUNK;
    const int tid   = threadIdx.x;
    if (tid < SEQ) hs[tid] = g_hpair[tid];

    const float* xb = x + (size_t)b * SEQ * DM + dbase;
#pragma unroll
    for (int it = 0; it < 6; it++) {
        int i = tid + it * 256;
        int s = i >> 4;
        int c = (i & 15) * 4;
        *(float4*)&xs[s * FCHUNK + c] = *(const float4*)(xb + (size_t)s * DM + c);
    }
    __syncthreads();

    float* xlb = g_xl + (size_t)b * SEQ * DM + dbase;
    float* xhb = g_xh + (size_t)b * SEQ * DM + dbase;
#pragma unroll
    for (int it = 0; it < 6; it++) {
        int i = tid + it * 256;
        int s = i >> 4;
        int c = (i & 15) * 4;

        float2 h0  = hs[0];
        float2 h48 = hs[48];
        float4 xv  = *(const float4*)&xs[s * FCHUNK + c];
        float4 al, ah;
        al.x = h0.x * xv.x; al.y = h0.x * xv.y; al.z = h0.x * xv.z; al.w = h0.x * xv.w;
        ah.x = h0.y * xv.x; ah.y = h0.y * xv.y; ah.z = h0.y * xv.z; ah.w = h0.y * xv.w;

        int s48 = (s >= 48) ? s - 48 : s + 48;
        float4 xm = *(const float4*)&xs[s48 * FCHUNK + c];
        al.x += h48.x * xm.x; al.y += h48.x * xm.y; al.z += h48.x * xm.z; al.w += h48.x * xm.w;
        ah.x += h48.y * xm.x; ah.y += h48.y * xm.y; ah.z += h48.y * xm.z; ah.w += h48.y * xm.w;

        int t1 = (s == 0)  ? 95 : s - 1;
        int t2 = (s == 95) ? 0  : s + 1;
#pragma unroll 4
        for (int u = 1; u < 48; u++) {
            float2 h  = hs[u];
            float4 x1 = *(const float4*)&xs[t1 * FCHUNK + c];
            float4 x2 = *(const float4*)&xs[t2 * FCHUNK + c];
            float p0 = x1.x + x2.x, p1 = x1.y + x2.y, p2 = x1.z + x2.z, p3 = x1.w + x2.w;
            al.x += h.x * p0; al.y += h.x * p1; al.z += h.x * p2; al.w += h.x * p3;
            ah.x += h.y * p0; ah.y += h.y * p1; ah.z += h.y * p2; ah.w += h.y * p3;
            t1--; if (t1 < 0)  t1 = 95;
            t2++; if (t2 > 95) t2 = 0;
        }
        // round to tf32 so the GEMM needs no conversion (rounding, NOT truncation)
        al.x = wmma::__float_to_tf32(al.x); al.y = wmma::__float_to_tf32(al.y);
        al.z = wmma::__float_to_tf32(al.z); al.w = wmma::__float_to_tf32(al.w);
        ah.x = wmma::__float_to_tf32(ah.x); ah.y = wmma::__float_to_tf32(ah.y);
        ah.z = wmma::__float_to_tf32(ah.z); ah.w = wmma::__float_to_tf32(ah.w);
        *(float4*)(xlb + (size_t)s * DM + c) = al;
        *(float4*)(xhb + (size_t)s * DM + c) = ah;
    }
}

// ---------------- pipelined tf32 wmma GEMM ----------------
// Block tile 128x128x32, 8 warps (2M x 4N), warp tile 64x32.
// Logical N = 1024 split into two halves with independent B/C pointers.
// cp.async double-buffered K pipeline; operands are pre-rounded tf32.
#define BM 128
#define BN 128
#define BK 32
#define LDA_S 36
#define LDB_S 136
#define STG_F (BM * LDA_S + BK * LDB_S)          // 8960 floats / stage
#define SMEM_BYTES (2 * STG_F * 4)               // 71680 B

__device__ __forceinline__ void cp16(float* dst, const float* src)
{
    unsigned d = (unsigned)__cvta_generic_to_shared(dst);
    asm volatile("cp.async.cg.shared.global [%0], [%1], 16;\n" :: "r"(d), "l"(src));
}

__device__ __forceinline__
void big_gemm_body(const float* __restrict__ A,
                   const float* __restrict__ B0, const float* __restrict__ B1,
                   float* __restrict__ C0, float* __restrict__ C1)
{
    extern __shared__ __align__(16) float sm[];

    const int bnl = blockIdx.x * BN;
    const float* B = (bnl >= DM) ? B1 : B0;
    float*       C = (bnl >= DM) ? C1 : C0;
    const int bn = bnl & (DM - 1);
    const int bm = blockIdx.y * BM;

    const int tid  = threadIdx.x;
    const int warp = tid >> 5;
    const int wm   = (warp & 1) * 64;
    const int wn   = (warp >> 1) * 32;

    const int a_r = tid >> 3, a_c = (tid & 7) << 2;   // A: 128x32, 4 float4/thread
    const int b_r = tid >> 5, b_c = (tid & 31) << 2;  // B: 32x128, 4 float4/thread
    const float* Ag = A + (size_t)(bm + a_r) * DM + a_c;
    const float* Bg = B + (size_t)b_r * DM + bn + b_c;

    wmma::fragment<wmma::accumulator, 16, 16, 8, float> acc[4][2];
#pragma unroll
    for (int i = 0; i < 4; i++)
#pragma unroll
        for (int j = 0; j < 2; j++)
            wmma::fill_fragment(acc[i][j], 0.0f);

    auto issue = [&](int k0, float* As, float* Bs) {
#pragma unroll
        for (int it = 0; it < 4; it++)
            cp16(&As[(a_r + it * 32) * LDA_S + a_c], Ag + (size_t)it * 32 * DM + k0);
#pragma unroll
        for (int it = 0; it < 4; it++)
            cp16(&Bs[(b_r + it * 8) * LDB_S + b_c], Bg + (size_t)(k0 + it * 8) * DM);
        asm volatile("cp.async.commit_group;\n");
    };

    issue(0, sm, sm + BM * LDA_S);

#pragma unroll 1
    for (int kt = 0; kt < DM / BK; kt++) {
        if (kt + 1 < DM / BK) {
            float* nb = sm + ((kt + 1) & 1) * STG_F;
            issue((kt + 1) * BK, nb, nb + BM * LDA_S);
            asm volatile("cp.async.wait_group 1;\n");
        } else {
            asm volatile("cp.async.wait_group 0;\n");
        }
        __syncthreads();

        float* As = sm + (kt & 1) * STG_F;
        float* Bs = As + BM * LDA_S;
#pragma unroll
        for (int kk = 0; kk < BK; kk += 8) {
            wmma::fragment<wmma::matrix_a, 16, 16, 8, wmma::precision::tf32, wmma::row_major> af[4];
            wmma::fragment<wmma::matrix_b, 16, 16, 8, wmma::precision::tf32, wmma::row_major> bf[2];
#pragma unroll
            for (int i = 0; i < 4; i++)
                wmma::load_matrix_sync(af[i], &As[(wm + i * 16) * LDA_S + kk], LDA_S);
#pragma unroll
            for (int j = 0; j < 2; j++)
                wmma::load_matrix_sync(bf[j], &Bs[kk * LDB_S + wn + j * 16], LDB_S);
#pragma unroll
            for (int i = 0; i < 4; i++)
#pragma unroll
                for (int j = 0; j < 2; j++)
                    wmma::mma_sync(acc[i][j], af[i], bf[j], acc[i][j]);
        }
        __syncthreads();
    }

#pragma unroll
    for (int i = 0; i < 4; i++)
#pragma unroll
        for (int j = 0; j < 2; j++)
            wmma::store_matrix_sync(C + (size_t)(bm + wm + i * 16) * DM + bn + wn + j * 16,
                                    acc[i][j], DM, wmma::mem_row_major);
}

// wrappers binding __device__ scratch
__global__ __launch_bounds__(256) void big_gemm_l()
{ big_gemm_body(g_xl, g_Wlr, g_Wlg, g_xlow2, g_gl); }

__global__ __launch_bounds__(256) void big_gemm_h()
{ big_gemm_body(g_xh, g_Whr, g_Whg, g_xhigh2, g_gh); }

// small weight-product GEMMs: M=512, grid (4,4,2); bnl < 512 so only B0/C0 used
__global__ __launch_bounds__(256) void small_gemm()
{
    if (blockIdx.z == 0)
        big_gemm_body(g_Wlr, g_Wgr, g_Wgr, g_Wlg, g_Wlg);
    else
        big_gemm_body(g_Whr, g_Wgr + DM * DM, g_Wgr + DM * DM, g_Whg, g_Whg);
}

// ---------------- fused gate + biases + residual + LayerNorm ----------------
__global__ __launch_bounds__(256)
void final_kernel(const float* __restrict__ x,
                  const float* __restrict__ bl,
                  const float* __restrict__ bh,
                  const float* __restrict__ gamma,
                  const float* __restrict__ beta,
                  float* __restrict__ out)
{
    const int r = blockIdx.x;
    const size_t base = (size_t)r * DM;
    const int tid = threadIdx.x;
    const int c = tid * 2;

    float2 xv  = *(const float2*)(x        + base + c);
    float2 lv  = *(const float2*)(g_xlow2  + base + c);
    float2 hv  = *(const float2*)(g_xhigh2 + base + c);
    float2 g1v = *(const float2*)(g_gl     + base + c);
    float2 g2v = *(const float2*)(g_gh     + base + c);
    float2 blv = *(const float2*)(bl       + c);
    float2 bhv = *(const float2*)(bh       + c);
    float2 bgv = *(const float2*)(g_biasg  + c);

    lv.x += blv.x; lv.y += blv.y;
    hv.x += bhv.x; hv.y += bhv.y;
    float p0 = g1v.x + g2v.x + bgv.x;
    float p1 = g1v.y + g2v.y + bgv.y;

    float g0 = 1.0f / (1.0f + __expf(-p0));
    float g1 = 1.0f / (1.0f + __expf(-p1));
    float y0 = xv.x + g0 * lv.x + (1.0f - g0) * hv.x;
    float y1 = xv.y + g1 * lv.y + (1.0f - g1) * hv.y;

    float s1 = y0 + y1;
    float s2 = y0 * y0 + y1 * y1;
#pragma unroll
    for (int o = 16; o > 0; o >>= 1) {
        s1 += __shfl_xor_sync(0xffffffffu, s1, o);
        s2 += __shfl_xor_sync(0xffffffffu, s2, o);
    }
    __shared__ float rs1[8], rs2[8];
    int warp = tid >> 5, lane = tid & 31;
    if (lane == 0) { rs1[warp] = s1; rs2[warp] = s2; }
    __syncthreads();
    float t1 = 0.f, t2 = 0.f;
#pragma unroll
    for (int w = 0; w < 8; w++) { t1 += rs1[w]; t2 += rs2[w]; }

    float mu   = t1 * (1.0f / DM);
    float var  = t2 * (1.0f / DM) - mu * mu;
    float rstd = rsqrtf(var + 1e-5f);

    float2 gm = *(const float2*)(gamma + c);
    float2 bt = *(const float2*)(beta  + c);
    float2 o2;
    o2.x = (y0 - mu) * rstd * gm.x + bt.x;
    o2.y = (y1 - mu) * rstd * gm.y + bt.y;
    *(float2*)(out + base + c) = o2;
}

// ---------------- launch ----------------
extern "C" void kernel_launch(void* const* d_in, const int* in_sizes, int n_in,
                              void* d_out, int out_size)
{
    const float* x     = (const float*)d_in[0];
    const float* fw    = (const float*)d_in[1];
    const float* Wl    = (const float*)d_in[2];
    const float* bl    = (const float*)d_in[3];
    const float* Wh    = (const float*)d_in[4];
    const float* bh    = (const float*)d_in[5];
    const float* Wg    = (const float*)d_in[6];
    const float* bg    = (const float*)d_in[7];
    const float* gamma = (const float*)d_in[8];
    const float* beta  = (const float*)d_in[9];
    float* out = (float*)d_out;

    cudaFuncSetAttribute(small_gemm, cudaFuncAttributeMaxDynamicSharedMemorySize, SMEM_BYTES);
    cudaFuncSetAttribute(big_gemm_l, cudaFuncAttributeMaxDynamicSharedMemorySize, SMEM_BYTES);
    cudaFuncSetAttribute(big_gemm_h, cudaFuncAttributeMaxDynamicSharedMemorySize, SMEM_BYTES);

    // prep: taps, folded bias, tf32-rounded weights, weight products
    h_kernel<<<1, 128>>>(fw);
    biasg_kernel<<<4, 128>>>(bl, bh, Wg, bg);
    round_w<<<1024, 256>>>(Wl, Wh, Wg);
    small_gemm<<<dim3(4, 4, 2), 256, SMEM_BYTES>>>();

    // spectral split as circular conv (writes tf32-rounded xl/xh)
    filter_kernel<<<dim3(DM / FCHUNK, BATCH), 256>>>(x);

    // two merged big GEMMs: [xlow2 | gl] and [xhigh2 | gh]
    dim3 gbig(1024 / BN, NROWS / BM);                 // (8, 384)
    big_gemm_l<<<gbig, 256, SMEM_BYTES>>>();
    big_gemm_h<<<gbig, 256, SMEM_BYTES>>>();

    // gate + residual + LayerNorm
    final_kernel<<<NROWS, 256>>>(x, bl, bh, gamma, beta, out);
}

// round 17
// speedup vs baseline: 1.1108x; 1.0016x over previous
#include <cuda_runtime.h>
#include <mma.h>
#include <cstdint>

using namespace nvcuda;

// ---------------- problem constants ----------------
#define DM      512
#define SEQ     96
#define BATCH   512
#define NROWS   (BATCH * SEQ)       // 49152
#define CUTOFF  16                  // FREQ(49) // 3

// ---------------- device scratch ----------------
__device__ float  g_xl[NROWS * DM];      // L*x   (tf32-rounded)
__device__ float  g_xh[NROWS * DM];      // H*x   (tf32-rounded)
__device__ float  g_xlow2[NROWS * DM];   // xl @ Wl           (no bias)
__device__ float  g_xhigh2[NROWS * DM];  // xh @ Wh           (no bias)
__device__ float  g_gl[NROWS * DM];      // xl @ Wlg          (no bias)
__device__ float  g_gh[NROWS * DM];      // xh @ Whg          (no bias)
__device__ float  g_Wlg[DM * DM];        // Wl @ Wg_top
__device__ float  g_Whg[DM * DM];        // Wh @ Wg_bot
__device__ float  g_Wlr[DM * DM];        // tf32-rounded Wl
__device__ float  g_Whr[DM * DM];        // tf32-rounded Wh
__device__ float  g_Wgr[2 * DM * DM];    // tf32-rounded Wg
__device__ float  g_biasg[DM];           // bl@Wg_top + bh@Wg_bot + bg
__device__ float2 g_hpair[SEQ];          // (h_low[u], h_high[u])

// ---------------- circular-conv taps from freq_weights ----------------
__global__ void h_kernel(const float* __restrict__ fw)
{
    int n = threadIdx.x;
    if (n >= SEQ) return;
    const float c0 = 6.2831853071795864769f / (float)SEQ;
    float hl = fw[0];
    for (int k = 1; k < CUTOFF; k++)
        hl += 2.0f * fw[k] * cosf((float)((k * n) % SEQ) * c0);
    float hh = 0.0f;
    for (int k = CUTOFF; k < 48; k++)
        hh += 2.0f * fw[k] * cosf((float)((k * n) % SEQ) * c0);
    hh += fw[48] * cosf((float)((48 * n) % SEQ) * c0);   // Nyquist once
    g_hpair[n] = make_float2(hl * (1.0f / SEQ), hh * (1.0f / SEQ));
}

// ---------------- folded gate bias ----------------
__global__ void biasg_kernel(const float* __restrict__ bl,
                             const float* __restrict__ bh,
                             const float* __restrict__ Wg,
                             const float* __restrict__ bg)
{
    int e = blockIdx.x * 128 + threadIdx.x;
    if (e >= DM) return;
    float acc = bg[e];
    for (int d = 0; d < DM; d++) acc += bl[d] * Wg[d * DM + e];
    for (int d = 0; d < DM; d++) acc += bh[d] * Wg[(DM + d) * DM + e];
    g_biasg[e] = acc;
}

// ---------------- tf32 rounding of weight operands ----------------
__global__ void round_w(const float* __restrict__ Wl,
                        const float* __restrict__ Wh,
                        const float* __restrict__ Wg)
{
    int i = blockIdx.x * 256 + threadIdx.x;          // 262144 threads exactly
    g_Wlr[i]           = wmma::__float_to_tf32(Wl[i]);
    g_Whr[i]           = wmma::__float_to_tf32(Wh[i]);
    g_Wgr[i]           = wmma::__float_to_tf32(Wg[i]);
    g_Wgr[i + DM * DM] = wmma::__float_to_tf32(Wg[i + DM * DM]);
}

// ---------------- filter: circular conv along seq, symmetric taps ----------------
// h[u] == h[96-u]  =>  al = h0*x[s] + h48*x[s-48] + sum_{u=1..47} h[u]*(x[s-u]+x[s+u])
#define FCHUNK 64
__global__ __launch_bounds__(256)
void filter_kernel(const float* __restrict__ x)
{
    __shared__ float  xs[SEQ * FCHUNK];
    __shared__ float2 hs[SEQ];
    const int b     = blockIdx.y;
    const int dbase = blockIdx.x * FCHUNK;
    const int tid   = threadIdx.x;
    if (tid < SEQ) hs[tid] = g_hpair[tid];

    const float* xb = x + (size_t)b * SEQ * DM + dbase;
#pragma unroll
    for (int it = 0; it < 6; it++) {
        int i = tid + it * 256;
        int s = i >> 4;
        int c = (i & 15) * 4;
        *(float4*)&xs[s * FCHUNK + c] = *(const float4*)(xb + (size_t)s * DM + c);
    }
    __syncthreads();

    float* xlb = g_xl + (size_t)b * SEQ * DM + dbase;
    float* xhb = g_xh + (size_t)b * SEQ * DM + dbase;
#pragma unroll
    for (int it = 0; it < 6; it++) {
        int i = tid + it * 256;
        int s = i >> 4;
        int c = (i & 15) * 4;

        float2 h0  = hs[0];
        float2 h48 = hs[48];
        float4 xv  = *(const float4*)&xs[s * FCHUNK + c];
        float4 al, ah;
        al.x = h0.x * xv.x; al.y = h0.x * xv.y; al.z = h0.x * xv.z; al.w = h0.x * xv.w;
        ah.x = h0.y * xv.x; ah.y = h0.y * xv.y; ah.z = h0.y * xv.z; ah.w = h0.y * xv.w;

        int s48 = (s >= 48) ? s - 48 : s + 48;
        float4 xm = *(const float4*)&xs[s48 * FCHUNK + c];
        al.x += h48.x * xm.x; al.y += h48.x * xm.y; al.z += h48.x * xm.z; al.w += h48.x * xm.w;
        ah.x += h48.y * xm.x; ah.y += h48.y * xm.y; ah.z += h48.y * xm.z; ah.w += h48.y * xm.w;

        int t1 = (s == 0)  ? 95 : s - 1;
        int t2 = (s == 95) ? 0  : s + 1;
#pragma unroll 4
        for (int u = 1; u < 48; u++) {
            float2 h  = hs[u];
            float4 x1 = *(const float4*)&xs[t1 * FCHUNK + c];
            float4 x2 = *(const float4*)&xs[t2 * FCHUNK + c];
            float p0 = x1.x + x2.x, p1 = x1.y + x2.y, p2 = x1.z + x2.z, p3 = x1.w + x2.w;
            al.x += h.x * p0; al.y += h.x * p1; al.z += h.x * p2; al.w += h.x * p3;
            ah.x += h.y * p0; ah.y += h.y * p1; ah.z += h.y * p2; ah.w += h.y * p3;
            t1--; if (t1 < 0)  t1 = 95;
            t2++; if (t2 > 95) t2 = 0;
        }
        // round to tf32 so the GEMM needs no conversion (rounding, NOT truncation)
        al.x = wmma::__float_to_tf32(al.x); al.y = wmma::__float_to_tf32(al.y);
        al.z = wmma::__float_to_tf32(al.z); al.w = wmma::__float_to_tf32(al.w);
        ah.x = wmma::__float_to_tf32(ah.x); ah.y = wmma::__float_to_tf32(ah.y);
        ah.z = wmma::__float_to_tf32(ah.z); ah.w = wmma::__float_to_tf32(ah.w);
        *(float4*)(xlb + (size_t)s * DM + c) = al;
        *(float4*)(xhb + (size_t)s * DM + c) = ah;
    }
}

// ---------------- pipelined tf32 wmma GEMM ----------------
// Block tile 128x128x32, 8 warps (2M x 4N), warp tile 64x32.
// Logical N = 1024 split into two halves with independent B/C pointers.
// cp.async double-buffered K pipeline; operands are pre-rounded tf32.
#define BM 128
#define BN 128
#define BK 32
#define LDA_S 36
#define LDB_S 136
#define STG_F (BM * LDA_S + BK * LDB_S)          // 8960 floats / stage
#define SMEM_BYTES (2 * STG_F * 4)               // 71680 B

__device__ __forceinline__ void cp16(float* dst, const float* src)
{
    unsigned d = (unsigned)__cvta_generic_to_shared(dst);
    asm volatile("cp.async.cg.shared.global [%0], [%1], 16;\n" :: "r"(d), "l"(src));
}

__device__ __forceinline__
void big_gemm_body(const float* __restrict__ A,
                   const float* __restrict__ B0, const float* __restrict__ B1,
                   float* __restrict__ C0, float* __restrict__ C1)
{
    extern __shared__ __align__(16) float sm[];

    const int bnl = blockIdx.x * BN;
    const float* B = (bnl >= DM) ? B1 : B0;
    float*       C = (bnl >= DM) ? C1 : C0;
    const int bn = bnl & (DM - 1);
    const int bm = blockIdx.y * BM;

    const int tid  = threadIdx.x;
    const int warp = tid >> 5;
    const int wm   = (warp & 1) * 64;
    const int wn   = (warp >> 1) * 32;

    const int a_r = tid >> 3, a_c = (tid & 7) << 2;   // A: 128x32, 4 float4/thread
    const int b_r = tid >> 5, b_c = (tid & 31) << 2;  // B: 32x128, 4 float4/thread
    const float* Ag = A + (size_t)(bm + a_r) * DM + a_c;
    const float* Bg = B + (size_t)b_r * DM + bn + b_c;

    wmma::fragment<wmma::accumulator, 16, 16, 8, float> acc[4][2];
#pragma unroll
    for (int i = 0; i < 4; i++)
#pragma unroll
        for (int j = 0; j < 2; j++)
            wmma::fill_fragment(acc[i][j], 0.0f);

    auto issue = [&](int k0, float* As, float* Bs) {
#pragma unroll
        for (int it = 0; it < 4; it++)
            cp16(&As[(a_r + it * 32) * LDA_S + a_c], Ag + (size_t)it * 32 * DM + k0);
#pragma unroll
        for (int it = 0; it < 4; it++)
            cp16(&Bs[(b_r + it * 8) * LDB_S + b_c], Bg + (size_t)(k0 + it * 8) * DM);
        asm volatile("cp.async.commit_group;\n");
    };

    issue(0, sm, sm + BM * LDA_S);

#pragma unroll 1
    for (int kt = 0; kt < DM / BK; kt++) {
        if (kt + 1 < DM / BK) {
            float* nb = sm + ((kt + 1) & 1) * STG_F;
            issue((kt + 1) * BK, nb, nb + BM * LDA_S);
            asm volatile("cp.async.wait_group 1;\n");
        } else {
            asm volatile("cp.async.wait_group 0;\n");
        }
        __syncthreads();

        float* As = sm + (kt & 1) * STG_F;
        float* Bs = As + BM * LDA_S;
#pragma unroll
        for (int kk = 0; kk < BK; kk += 8) {
            wmma::fragment<wmma::matrix_a, 16, 16, 8, wmma::precision::tf32, wmma::row_major> af[4];
            wmma::fragment<wmma::matrix_b, 16, 16, 8, wmma::precision::tf32, wmma::row_major> bf[2];
#pragma unroll
            for (int i = 0; i < 4; i++)
                wmma::load_matrix_sync(af[i], &As[(wm + i * 16) * LDA_S + kk], LDA_S);
#pragma unroll
            for (int j = 0; j < 2; j++)
                wmma::load_matrix_sync(bf[j], &Bs[kk * LDB_S + wn + j * 16], LDB_S);
#pragma unroll
            for (int i = 0; i < 4; i++)
#pragma unroll
                for (int j = 0; j < 2; j++)
                    wmma::mma_sync(acc[i][j], af[i], bf[j], acc[i][j]);
        }
        __syncthreads();
    }

#pragma unroll
    for (int i = 0; i < 4; i++)
#pragma unroll
        for (int j = 0; j < 2; j++)
            wmma::store_matrix_sync(C + (size_t)(bm + wm + i * 16) * DM + bn + wn + j * 16,
                                    acc[i][j], DM, wmma::mem_row_major);
}

// wrappers binding __device__ scratch
__global__ __launch_bounds__(256) void big_gemm_l()
{ big_gemm_body(g_xl, g_Wlr, g_Wlg, g_xlow2, g_gl); }

__global__ __launch_bounds__(256) void big_gemm_h()
{ big_gemm_body(g_xh, g_Whr, g_Whg, g_xhigh2, g_gh); }

// small weight-product GEMMs: M=512, grid (4,4,2); bnl < 512 so only B0/C0 used
__global__ __launch_bounds__(256) void small_gemm()
{
    if (blockIdx.z == 0)
        big_gemm_body(g_Wlr, g_Wgr, g_Wgr, g_Wlg, g_Wlg);
    else
        big_gemm_body(g_Whr, g_Wgr + DM * DM, g_Wgr + DM * DM, g_Whg, g_Whg);
}

// ---------------- fused gate + biases + residual + LayerNorm ----------------
__global__ __launch_bounds__(256)
void final_kernel(const float* __restrict__ x,
                  const float* __restrict__ bl,
                  const float* __restrict__ bh,
                  const float* __restrict__ gamma,
                  const float* __restrict__ beta,
                  float* __restrict__ out)
{
    const int r = blockIdx.x;
    const size_t base = (size_t)r * DM;
    const int tid = threadIdx.x;
    const int c = tid * 2;

    float2 xv  = *(const float2*)(x        + base + c);
    float2 lv  = *(const float2*)(g_xlow2  + base + c);
    float2 hv  = *(const float2*)(g_xhigh2 + base + c);
    float2 g1v = *(const float2*)(g_gl     + base + c);
    float2 g2v = *(const float2*)(g_gh     + base + c);
    float2 blv = *(const float2*)(bl       + c);
    float2 bhv = *(const float2*)(bh       + c);
    float2 bgv = *(const float2*)(g_biasg  + c);

    lv.x += blv.x; lv.y += blv.y;
    hv.x += bhv.x; hv.y += bhv.y;
    float p0 = g1v.x + g2v.x + bgv.x;
    float p1 = g1v.y + g2v.y + bgv.y;

    float g0 = 1.0f / (1.0f + __expf(-p0));
    float g1 = 1.0f / (1.0f + __expf(-p1));
    float y0 = xv.x + g0 * lv.x + (1.0f - g0) * hv.x;
    float y1 = xv.y + g1 * lv.y + (1.0f - g1) * hv.y;

    float s1 = y0 + y1;
    float s2 = y0 * y0 + y1 * y1;
#pragma unroll
    for (int o = 16; o > 0; o >>= 1) {
        s1 += __shfl_xor_sync(0xffffffffu, s1, o);
        s2 += __shfl_xor_sync(0xffffffffu, s2, o);
    }
    __shared__ float rs1[8], rs2[8];
    int warp = tid >> 5, lane = tid & 31;
    if (lane == 0) { rs1[warp] = s1; rs2[warp] = s2; }
    __syncthreads();
    float t1 = 0.f, t2 = 0.f;
#pragma unroll
    for (int w = 0; w < 8; w++) { t1 += rs1[w]; t2 += rs2[w]; }

    float mu   = t1 * (1.0f / DM);
    float var  = t2 * (1.0f / DM) - mu * mu;
    float rstd = rsqrtf(var + 1e-5f);

    float2 gm = *(const float2*)(gamma + c);
    float2 bt = *(const float2*)(beta  + c);
    float2 o2;
    o2.x = (y0 - mu) * rstd * gm.x + bt.x;
    o2.y = (y1 - mu) * rstd * gm.y + bt.y;
    *(float2*)(out + base + c) = o2;
}

// ---------------- launch ----------------
extern "C" void kernel_launch(void* const* d_in, const int* in_sizes, int n_in,
                              void* d_out, int out_size)
{
    const float* x     = (const float*)d_in[0];
    const float* fw    = (const float*)d_in[1];
    const float* Wl    = (const float*)d_in[2];
    const float* bl    = (const float*)d_in[3];
    const float* Wh    = (const float*)d_in[4];
    const float* bh    = (const float*)d_in[5];
    const float* Wg    = (const float*)d_in[6];
    const float* bg    = (const float*)d_in[7];
    const float* gamma = (const float*)d_in[8];
    const float* beta  = (const float*)d_in[9];
    float* out = (float*)d_out;

    cudaFuncSetAttribute(small_gemm, cudaFuncAttributeMaxDynamicSharedMemorySize, SMEM_BYTES);
    cudaFuncSetAttribute(big_gemm_l, cudaFuncAttributeMaxDynamicSharedMemorySize, SMEM_BYTES);
    cudaFuncSetAttribute(big_gemm_h, cudaFuncAttributeMaxDynamicSharedMemorySize, SMEM_BYTES);

    // prep: taps, folded bias, tf32-rounded weights, weight products
    h_kernel<<<1, 128>>>(fw);
    biasg_kernel<<<4, 128>>>(bl, bh, Wg, bg);
    round_w<<<1024, 256>>>(Wl, Wh, Wg);
    small_gemm<<<dim3(4, 4, 2), 256, SMEM_BYTES>>>();

    // spectral split as circular conv (writes tf32-rounded xl/xh)
    filter_kernel<<<dim3(DM / FCHUNK, BATCH), 256>>>(x);

    // two merged big GEMMs: [xlow2 | gl] and [xhigh2 | gh]
    dim3 gbig(1024 / BN, NROWS / BM);                 // (8, 384)
    big_gemm_l<<<gbig, 256, SMEM_BYTES>>>();
    big_gemm_h<<<gbig, 256, SMEM_BYTES>>>();

    // gate + residual + LayerNorm
    final_kernel<<<NROWS, 256>>>(x, bl, bh, gamma, beta, out);
}